// round 17
// baseline (speedup 1.0000x reference)
#include <cuda_runtime.h>
#include <cstdint>

#define CC  192
#define BB  8
#define HH  96
#define WW  96
#define HWH (HH*WW)     // 9216
#define CO  64
#define TH2 16          // dw tile height (2 rows per thread)
#define WPS_STRIDE 66   // padded stride for transposed wp in smem

// ReLU'd depthwise output, [B][C][H][W]
__device__ float g_scratch[BB * CC * HH * WW];

// ---------------------------------------------------------------------------
// f32x2 helpers (bit-exact fp32 per lane)
// ---------------------------------------------------------------------------
__device__ __forceinline__ uint64_t pack2(float lo, float hi) {
    uint64_t r; asm("mov.b64 %0, {%1, %2};" : "=l"(r) : "f"(lo), "f"(hi)); return r;
}
__device__ __forceinline__ void unpack2(uint64_t v, float& lo, float& hi) {
    asm("mov.b64 {%0, %1}, %2;" : "=f"(lo), "=f"(hi) : "l"(v));
}
__device__ __forceinline__ void fma2(uint64_t& d, uint64_t a, uint64_t b) {
    asm("fma.rn.f32x2 %0, %1, %2, %0;" : "+l"(d) : "l"(a), "l"(b));
}

// ---------------------------------------------------------------------------
// Fused depthwise (65 folded taps) + ReLU, f32x2-packed.
// Block (24,8)=192 thr; tile = 96 wide x 16 rows of one (b,c) plane.
// Each thread: 2 output rows x 4 px. Weight fold done in-block (no prep kernel).
// Tap layout: [0..48] dense 7x7 row-major (dy,dx in -3..3);
//             [49..56] dil-5 ring; [57..64] dil-7 ring (row-major, skip center).
// ---------------------------------------------------------------------------
__global__ __launch_bounds__(192, 2) void dw_kernel(const float* __restrict__ x,
                                                    const float* __restrict__ a,
                                                    const float* __restrict__ w1,
                                                    const float* __restrict__ w3,
                                                    const float* __restrict__ w5,
                                                    const float* __restrict__ w7,
                                                    const float* __restrict__ w35,
                                                    const float* __restrict__ w37) {
    __shared__ __align__(16) float s[30][112];  // rows y0-7..y0+22, cols -7..102
    __shared__ __align__(8)  float2 ws2[66];

    const int c = blockIdx.y, b = blockIdx.z;
    const int y0 = blockIdx.x * TH2;
    const int tid = threadIdx.y * 24 + threadIdx.x;

    // ---- in-block weight fold (threads 0..64) ----
    if (tid < 65) {
        float a0 = a[0], a1 = a[1], a25 = a[2] + a[5], a3 = a[3], a4 = a[4];
        float a6 = a[6], a7 = a[7];
        float v;
        if (tid < 49) {
            int ky = tid / 7, kx = tid - ky * 7;
            int dy = ky - 3, dx = kx - 3;
            v = a4 * w7[c * 49 + tid];
            if (dy >= -2 && dy <= 2 && dx >= -2 && dx <= 2)
                v += a3 * w5[c * 25 + (dy + 2) * 5 + (dx + 2)];
            if (dy >= -1 && dy <= 1 && dx >= -1 && dx <= 1)
                v += a25 * w3[c * 9 + (dy + 1) * 3 + (dx + 1)];
            if (tid == 24)
                v += a0 + a1 * w1[c] + a6 * w35[c * 9 + 4] + a7 * w37[c * 9 + 4];
        } else {
            int t = tid - 49;          // 0..15
            int g = t & 7;             // ring position, row-major skipping center
            int gg = g + (g >= 4);     // 0,1,2,3,5,6,7,8
            int i = gg / 3, j = gg - i * 3;
            v = (t < 8) ? a6 * w35[c * 9 + i * 3 + j]
                        : a7 * w37[c * 9 + i * 3 + j];
        }
        ws2[tid] = make_float2(v, v);
    }

    // ---- halo tile load ----
    const float* __restrict__ xp = x + (size_t)(b * CC + c) * HWH;
    for (int i = tid; i < 30 * 110; i += 192) {
        int sy = i / 110, sx = i - sy * 110;
        int gy = y0 + sy - 7, gx = sx - 7;
        float v = 0.f;
        if (gy >= 0 && gy < HH && (unsigned)gx < (unsigned)WW) v = xp[gy * WW + gx];
        s[sy][sx] = v;
    }
    __syncthreads();

    const int tx = threadIdx.x, ty = threadIdx.y;
    const int ox = tx * 4;
    const int yb = 2 * ty;              // local out rows yb, yb+1
    const uint64_t* wq = (const uint64_t*)ws2;

    uint64_t acc0A = 0ull, acc0B = 0ull;   // out row yb:   (p0,p1),(p2,p3)
    uint64_t acc1A = 0ull, acc1B = 0ull;   // out row yb+1

    // ---- dense 7x7, 8 shared input rows; weight rows reused across out rows
    uint64_t wprev[7];
#pragma unroll
    for (int r = 0; r < 8; r++) {
        const float* rowp = &s[yb + 4 + r][ox + 4];
        float4 ra = *(const float4*)rowp;
        float4 rb = *(const float4*)(rowp + 4);
        float2 rc = *(const float2*)(rowp + 8);
        float rr[10] = {ra.x, ra.y, ra.z, ra.w, rb.x, rb.y, rb.z, rb.w, rc.x, rc.y};
        uint64_t pe[5], po[4];
#pragma unroll
        for (int i = 0; i < 5; i++) pe[i] = pack2(rr[2 * i], rr[2 * i + 1]);
#pragma unroll
        for (int i = 0; i < 4; i++) po[i] = pack2(rr[2 * i + 1], rr[2 * i + 2]);

        uint64_t wcur[7];
        if (r < 7) {
#pragma unroll
            for (int kx = 0; kx < 7; kx++) wcur[kx] = wq[r * 7 + kx];
        }
#pragma unroll
        for (int kx = 0; kx < 7; kx++) {
            uint64_t i0 = (kx & 1) ? po[(kx - 1) >> 1] : pe[kx >> 1];
            uint64_t i1 = (kx & 1) ? po[(kx + 1) >> 1] : pe[(kx >> 1) + 1];
            if (r < 7)  { fma2(acc0A, wcur[kx],  i0); fma2(acc0B, wcur[kx],  i1); }
            if (r >= 1) { fma2(acc1A, wprev[kx], i0); fma2(acc1B, wprev[kx], i1); }
        }
        if (r < 7) {
#pragma unroll
            for (int kx = 0; kx < 7; kx++) wprev[kx] = wcur[kx];
        }
    }

    // ---- sparse ring taps (both out rows); 8B-aligned LDS.64 when 7+dx is even
#define TAP_EVEN(widx, dy, dx)                                                  \
    { uint64_t w2 = wq[widx];                                                   \
      const float* p0 = &s[yb + 7 + (dy)][ox + 7 + (dx)];                       \
      const float* p1 = &s[yb + 8 + (dy)][ox + 7 + (dx)];                       \
      fma2(acc0A, w2, *(const uint64_t*)p0);                                    \
      fma2(acc0B, w2, *(const uint64_t*)(p0 + 2));                              \
      fma2(acc1A, w2, *(const uint64_t*)p1);                                    \
      fma2(acc1B, w2, *(const uint64_t*)(p1 + 2)); }
#define TAP_ODD(widx, dy, dx)                                                   \
    { uint64_t w2 = wq[widx];                                                   \
      const float* p0 = &s[yb + 7 + (dy)][ox + 7 + (dx)];                       \
      const float* p1 = &s[yb + 8 + (dy)][ox + 7 + (dx)];                       \
      fma2(acc0A, w2, pack2(p0[0], p0[1]));                                     \
      fma2(acc0B, w2, pack2(p0[2], p0[3]));                                     \
      fma2(acc1A, w2, pack2(p1[0], p1[1]));                                     \
      fma2(acc1B, w2, pack2(p1[2], p1[3])); }

    TAP_EVEN(49, -5, -5) TAP_ODD(50, -5, 0) TAP_EVEN(51, -5, 5)
    TAP_EVEN(52,  0, -5)                    TAP_EVEN(53,  0, 5)
    TAP_EVEN(54,  5, -5) TAP_ODD(55,  5, 0) TAP_EVEN(56,  5, 5)

    TAP_EVEN(57, -7, -7) TAP_ODD(58, -7, 0) TAP_EVEN(59, -7, 7)
    TAP_EVEN(60,  0, -7)                    TAP_EVEN(61,  0, 7)
    TAP_EVEN(62,  7, -7) TAP_ODD(63,  7, 0) TAP_EVEN(64,  7, 7)
#undef TAP_EVEN
#undef TAP_ODD

    float v0, v1, v2, v3;
    float* outp = &g_scratch[(size_t)(b * CC + c) * HWH + (y0 + yb) * WW + ox];
    unpack2(acc0A, v0, v1); unpack2(acc0B, v2, v3);
    *(float4*)outp = make_float4(fmaxf(v0, 0.f), fmaxf(v1, 0.f),
                                 fmaxf(v2, 0.f), fmaxf(v3, 0.f));
    unpack2(acc1A, v0, v1); unpack2(acc1B, v2, v3);
    *(float4*)(outp + WW) = make_float4(fmaxf(v0, 0.f), fmaxf(v1, 0.f),
                                        fmaxf(v2, 0.f), fmaxf(v3, 0.f));
}

// ---------------------------------------------------------------------------
// Pointwise 1x1: out[b,o,p] = sum_c wp[o,c] * relu[b,c,p]
// 64 outs x 64 px tile, K=192. 128 thr = (16 px-quads, 8 o-groups), 8 outs x 4 px
// per thread. Scratch staged as SCALAR floats (conflict-free LDS.128 reads and
// STS.32 writes); per-kc lane-duplication via 4 ALU packs (overlaps fma pipe).
// Next chunk's gmem loads prefetched into registers under the fma loop.
// ---------------------------------------------------------------------------
extern __shared__ float pw_smem[];

__global__ __launch_bounds__(128, 4) void pw_kernel(const float* __restrict__ wp,
                                                    float* __restrict__ out) {
    float* wps = pw_smem;                      // transposed wp: [c][66] (o fast)
    float* ss  = pw_smem + CC * WPS_STRIDE;    // [16][64] scalar scratch chunk

    const int tid = threadIdx.x;
    const int b = blockIdx.y;
    const int px0 = blockIdx.x * 64;

    // load + transpose wp (wp is [o][c], c fast -> coalesced reads)
    for (int i = tid; i < CO * CC; i += 128) {
        int o = i / CC, cc = i - o * CC;
        wps[cc * WPS_STRIDE + o] = wp[i];
    }

    const int tx = tid & 15, og = tid >> 4;
    const float* sb = g_scratch + (size_t)b * CC * HWH + px0;

    // per-thread staging addresses: 8 elements, ii = tid + i*128
    int skc[8], sp_[8];
#pragma unroll
    for (int i = 0; i < 8; i++) {
        int ii = tid + i * 128;
        skc[i] = ii >> 6; sp_[i] = ii & 63;
    }

    uint64_t acc[4][4];
#pragma unroll
    for (int i = 0; i < 4; i++)
#pragma unroll
        for (int j = 0; j < 4; j++) acc[i][j] = 0ull;

    // prefetch chunk 0
    float vbuf[8];
#pragma unroll
    for (int i = 0; i < 8; i++)
        vbuf[i] = sb[(size_t)skc[i] * HWH + sp_[i]];

    for (int c0 = 0; c0 < CC; c0 += 16) {
        __syncthreads();   // first iter: wps ready; later: prev chunk readers done
#pragma unroll
        for (int i = 0; i < 8; i++)
            ss[skc[i] * 64 + sp_[i]] = vbuf[i];
        __syncthreads();

        // issue next chunk's gmem loads; scoreboard drains under the fma loop
        if (c0 + 16 < CC) {
#pragma unroll
            for (int i = 0; i < 8; i++)
                vbuf[i] = sb[(size_t)(c0 + 16 + skc[i]) * HWH + sp_[i]];
        }

#pragma unroll
        for (int kc = 0; kc < 16; kc++) {
            float4 sv = *(const float4*)&ss[kc * 64 + tx * 4];
            uint64_t s0 = pack2(sv.x, sv.x), s1 = pack2(sv.y, sv.y);
            uint64_t s2 = pack2(sv.z, sv.z), s3 = pack2(sv.w, sv.w);
            const float* wrow = &wps[(c0 + kc) * WPS_STRIDE + og * 8];
#pragma unroll
            for (int op = 0; op < 4; op++) {
                uint64_t w2 = *(const uint64_t*)(wrow + op * 2);  // (w[o], w[o+1])
                fma2(acc[op][0], w2, s0);
                fma2(acc[op][1], w2, s1);
                fma2(acc[op][2], w2, s2);
                fma2(acc[op][3], w2, s3);
            }
        }
    }

    float* ob = out + (size_t)b * CO * HWH + px0 + tx * 4;
#pragma unroll
    for (int op = 0; op < 4; op++) {
        float lo0, hi0, lo1, hi1, lo2, hi2, lo3, hi3;
        unpack2(acc[op][0], lo0, hi0);
        unpack2(acc[op][1], lo1, hi1);
        unpack2(acc[op][2], lo2, hi2);
        unpack2(acc[op][3], lo3, hi3);
        int o = og * 8 + op * 2;
        *(float4*)&ob[(size_t)o * HWH]       = make_float4(lo0, lo1, lo2, lo3);
        *(float4*)&ob[(size_t)(o + 1) * HWH] = make_float4(hi0, hi1, hi2, hi3);
    }
}

// ---------------------------------------------------------------------------
extern "C" void kernel_launch(void* const* d_in, const int* in_sizes, int n_in,
                              void* d_out, int out_size) {
    const float* x   = (const float*)d_in[0];
    const float* a   = (const float*)d_in[1];
    const float* w1  = (const float*)d_in[2];
    const float* w3  = (const float*)d_in[3];
    const float* w5  = (const float*)d_in[4];
    const float* w7  = (const float*)d_in[5];
    const float* w35 = (const float*)d_in[6];
    const float* w37 = (const float*)d_in[7];
    const float* wp  = (const float*)d_in[8];
    float* out = (float*)d_out;

    const int pw_smem_bytes =
        (CC * WPS_STRIDE + 16 * 64) * (int)sizeof(float);   // 54784
    cudaFuncSetAttribute(pw_kernel, cudaFuncAttributeMaxDynamicSharedMemorySize,
                         pw_smem_bytes);

    dw_kernel<<<dim3(HH / TH2, CC, BB), dim3(24, 8)>>>(x, a, w1, w3, w5, w7, w35, w37);
    pw_kernel<<<dim3(HWH / 64, BB), 128, pw_smem_bytes>>>(wp, out);
}